// round 3
// baseline (speedup 1.0000x reference)
#include <cuda_runtime.h>

// Problem constants
constexpr int NB  = 2;
constexpr int NS  = 2048;
constexpr int ND  = 1024;
constexpr int NH  = 16;
constexpr int NHD = 64;
constexpr int NM  = NB * NS;          // 4096 rows

// Scratch (allocation-free rule: device globals)
__device__ float g_q[NM * ND];
__device__ float g_k[NM * ND];
__device__ float g_v[NM * ND];
__device__ float g_att[NM * ND];

// ---------------------------------------------------------------------------
// GEMM: Y[M,N] = X[M,K] @ W[N,K]^T + bias   (M=4096, N=K=1024)
// 64x64 tile, BK=16, 256 threads, 4x4 micro-tile per thread.
// Smem k-major with pitch 68 (float4-aligned, conflict-light).
// ---------------------------------------------------------------------------
__global__ __launch_bounds__(256) void gemm_xwT_kernel(
    const float* __restrict__ X, const float* __restrict__ W,
    const float* __restrict__ bias, float* __restrict__ Y)
{
    constexpr int K = ND, N = ND;
    __shared__ float XsT[16 * 68];
    __shared__ float WsT[16 * 68];

    const int tid = threadIdx.x;
    const int ty = tid >> 4, tx = tid & 15;
    const int m0 = blockIdx.y * 64, n0 = blockIdx.x * 64;
    const int lr = tid >> 2, lc4 = tid & 3;   // loader: row, float4-col

    float acc[4][4] = {};

    for (int k0 = 0; k0 < K; k0 += 16) {
        float4 xv = *(const float4*)&X[(size_t)(m0 + lr) * K + k0 + 4 * lc4];
        float4 wv = *(const float4*)&W[(size_t)(n0 + lr) * K + k0 + 4 * lc4];
        __syncthreads();   // previous compute done reading smem
        XsT[(4 * lc4 + 0) * 68 + lr] = xv.x;
        XsT[(4 * lc4 + 1) * 68 + lr] = xv.y;
        XsT[(4 * lc4 + 2) * 68 + lr] = xv.z;
        XsT[(4 * lc4 + 3) * 68 + lr] = xv.w;
        WsT[(4 * lc4 + 0) * 68 + lr] = wv.x;
        WsT[(4 * lc4 + 1) * 68 + lr] = wv.y;
        WsT[(4 * lc4 + 2) * 68 + lr] = wv.z;
        WsT[(4 * lc4 + 3) * 68 + lr] = wv.w;
        __syncthreads();

        #pragma unroll
        for (int kk = 0; kk < 16; kk++) {
            float4 a = *(const float4*)&XsT[kk * 68 + 4 * ty];
            float4 b = *(const float4*)&WsT[kk * 68 + 4 * tx];
            acc[0][0] += a.x * b.x; acc[0][1] += a.x * b.y; acc[0][2] += a.x * b.z; acc[0][3] += a.x * b.w;
            acc[1][0] += a.y * b.x; acc[1][1] += a.y * b.y; acc[1][2] += a.y * b.z; acc[1][3] += a.y * b.w;
            acc[2][0] += a.z * b.x; acc[2][1] += a.z * b.y; acc[2][2] += a.z * b.z; acc[2][3] += a.z * b.w;
            acc[3][0] += a.w * b.x; acc[3][1] += a.w * b.y; acc[3][2] += a.w * b.z; acc[3][3] += a.w * b.w;
        }
    }

    float4 bv = *(const float4*)&bias[n0 + 4 * tx];
    #pragma unroll
    for (int i = 0; i < 4; i++) {
        float4 o;
        o.x = acc[i][0] + bv.x;
        o.y = acc[i][1] + bv.y;
        o.z = acc[i][2] + bv.z;
        o.w = acc[i][3] + bv.w;
        *(float4*)&Y[(size_t)(m0 + 4 * ty + i) * N + n0 + 4 * tx] = o;
    }
}

// ---------------------------------------------------------------------------
// Flash-style causal attention, fp32.
// grid: (S/64 q-tiles, B*H). block: 256 threads (16x16), 4x4 micro-tiles.
// Dynamic smem: QsT[64][68] (d-major), KsT[64][68] (d-major, aliased by P),
//               Vs[64][68] (k-major).
// Tiles are 64x64: each thread loads 4 float4s (column stripes 16*cc + 4*lc4).
// ---------------------------------------------------------------------------
__global__ __launch_bounds__(256) void attn_kernel(
    const float* __restrict__ Q, const float* __restrict__ Kg,
    const float* __restrict__ V, float* __restrict__ O)
{
    extern __shared__ float sm[];
    float* QsT = sm;                 // [d][q-row], pitch 68
    float* KsT = sm + 64 * 68;       // [d][k-col], pitch 68; reused as P[q][k]
    float* Vs  = sm + 2 * 64 * 68;   // [k][d], pitch 68

    const int tid = threadIdx.x;
    const int ty = tid >> 4, tx = tid & 15;
    const int qt = blockIdx.x;
    const int bh = blockIdx.y;
    const int b = bh >> 4, h = bh & 15;
    const int q0 = qt * 64;
    const size_t rowbase = (size_t)b * NS;
    const int coff = h * NHD;

    const int lr = tid >> 2, lc4 = tid & 3;

    // Load Q tile (64x64), transposed into d-major smem
    #pragma unroll
    for (int cc = 0; cc < 4; cc++) {
        const int c0 = 16 * cc + 4 * lc4;
        float4 qv = *(const float4*)&Q[(rowbase + q0 + lr) * ND + coff + c0];
        QsT[(c0 + 0) * 68 + lr] = qv.x;
        QsT[(c0 + 1) * 68 + lr] = qv.y;
        QsT[(c0 + 2) * 68 + lr] = qv.z;
        QsT[(c0 + 3) * 68 + lr] = qv.w;
    }

    float m_i[4], l_i[4];
    float acc[4][4] = {};
    #pragma unroll
    for (int i = 0; i < 4; i++) { m_i[i] = -1e30f; l_i[i] = 0.f; }

    __syncthreads();

    for (int kt = 0; kt <= qt; kt++) {
        const int k0 = kt * 64;
        float4 kv[4], vv[4];
        #pragma unroll
        for (int cc = 0; cc < 4; cc++) {
            const int c0 = 16 * cc + 4 * lc4;
            kv[cc] = *(const float4*)&Kg[(rowbase + k0 + lr) * ND + coff + c0];
            vv[cc] = *(const float4*)&V [(rowbase + k0 + lr) * ND + coff + c0];
        }
        __syncthreads();   // prior P@V done with KsT(P)/Vs
        #pragma unroll
        for (int cc = 0; cc < 4; cc++) {
            const int c0 = 16 * cc + 4 * lc4;
            KsT[(c0 + 0) * 68 + lr] = kv[cc].x;
            KsT[(c0 + 1) * 68 + lr] = kv[cc].y;
            KsT[(c0 + 2) * 68 + lr] = kv[cc].z;
            KsT[(c0 + 3) * 68 + lr] = kv[cc].w;
            *(float4*)&Vs[lr * 68 + c0] = vv[cc];
        }
        __syncthreads();

        // S = Q @ K^T  (4x4 per thread)
        float sv[4][4] = {};
        #pragma unroll 8
        for (int d = 0; d < 64; d++) {
            float4 a = *(const float4*)&QsT[d * 68 + 4 * ty];
            float4 bq = *(const float4*)&KsT[d * 68 + 4 * tx];
            sv[0][0] += a.x * bq.x; sv[0][1] += a.x * bq.y; sv[0][2] += a.x * bq.z; sv[0][3] += a.x * bq.w;
            sv[1][0] += a.y * bq.x; sv[1][1] += a.y * bq.y; sv[1][2] += a.y * bq.z; sv[1][3] += a.y * bq.w;
            sv[2][0] += a.z * bq.x; sv[2][1] += a.z * bq.y; sv[2][2] += a.z * bq.z; sv[2][3] += a.z * bq.w;
            sv[3][0] += a.w * bq.x; sv[3][1] += a.w * bq.y; sv[3][2] += a.w * bq.z; sv[3][3] += a.w * bq.w;
        }

        const bool diag = (kt == qt);

        // Online softmax per row
        #pragma unroll
        for (int i = 0; i < 4; i++) {
            const int qrow = 4 * ty + i;
            float rowmax = -1e30f;
            #pragma unroll
            for (int j = 0; j < 4; j++) {
                float s = sv[i][j] * 0.125f;   // 1/sqrt(64)
                if (diag && (4 * tx + j) > qrow) s = -1e30f;
                sv[i][j] = s;
                rowmax = fmaxf(rowmax, s);
            }
            #pragma unroll
            for (int off = 8; off >= 1; off >>= 1)
                rowmax = fmaxf(rowmax, __shfl_xor_sync(0xffffffffu, rowmax, off));

            float mnew = fmaxf(m_i[i], rowmax);
            float corr = __expf(m_i[i] - mnew);
            float rs = 0.f;
            #pragma unroll
            for (int j = 0; j < 4; j++) {
                float p = __expf(sv[i][j] - mnew);
                sv[i][j] = p;
                rs += p;
            }
            #pragma unroll
            for (int off = 8; off >= 1; off >>= 1)
                rs += __shfl_xor_sync(0xffffffffu, rs, off);

            l_i[i] = l_i[i] * corr + rs;
            m_i[i] = mnew;
            #pragma unroll
            for (int j = 0; j < 4; j++) acc[i][j] *= corr;
        }

        __syncthreads();   // all S-compute reads of KsT done
        float* Ps = KsT;   // alias
        #pragma unroll
        for (int i = 0; i < 4; i++) {
            float4 p4 = make_float4(sv[i][0], sv[i][1], sv[i][2], sv[i][3]);
            *(float4*)&Ps[(4 * ty + i) * 68 + 4 * tx] = p4;
        }
        __syncthreads();

        // O += P @ V
        #pragma unroll 8
        for (int kk = 0; kk < 64; kk++) {
            float4 v4 = *(const float4*)&Vs[kk * 68 + 4 * tx];
            float p0 = Ps[(4 * ty + 0) * 68 + kk];
            float p1 = Ps[(4 * ty + 1) * 68 + kk];
            float p2 = Ps[(4 * ty + 2) * 68 + kk];
            float p3 = Ps[(4 * ty + 3) * 68 + kk];
            acc[0][0] += p0 * v4.x; acc[0][1] += p0 * v4.y; acc[0][2] += p0 * v4.z; acc[0][3] += p0 * v4.w;
            acc[1][0] += p1 * v4.x; acc[1][1] += p1 * v4.y; acc[1][2] += p1 * v4.z; acc[1][3] += p1 * v4.w;
            acc[2][0] += p2 * v4.x; acc[2][1] += p2 * v4.y; acc[2][2] += p2 * v4.z; acc[2][3] += p2 * v4.w;
            acc[3][0] += p3 * v4.x; acc[3][1] += p3 * v4.y; acc[3][2] += p3 * v4.z; acc[3][3] += p3 * v4.w;
        }
    }

    // Finalize and write [B,S,D] layout (head h at columns h*64..)
    #pragma unroll
    for (int i = 0; i < 4; i++) {
        float inv = 1.f / l_i[i];
        float4 o = make_float4(acc[i][0] * inv, acc[i][1] * inv,
                               acc[i][2] * inv, acc[i][3] * inv);
        *(float4*)&O[(rowbase + q0 + 4 * ty + i) * ND + coff + 4 * tx] = o;
    }
}

// ---------------------------------------------------------------------------
extern "C" void kernel_launch(void* const* d_in, const int* in_sizes, int n_in,
                              void* d_out, int out_size)
{
    const float* x  = (const float*)d_in[0];
    const float* Wq = (const float*)d_in[1];
    const float* bq = (const float*)d_in[2];
    const float* Wk = (const float*)d_in[3];
    const float* bk = (const float*)d_in[4];
    const float* Wv = (const float*)d_in[5];
    const float* bv = (const float*)d_in[6];
    const float* Wf = (const float*)d_in[7];
    const float* bf = (const float*)d_in[8];
    float* out = (float*)d_out;

    void *pq, *pk, *pv, *patt;
    cudaGetSymbolAddress(&pq,  g_q);
    cudaGetSymbolAddress(&pk,  g_k);
    cudaGetSymbolAddress(&pv,  g_v);
    cudaGetSymbolAddress(&patt, g_att);

    const int smem_attn = 3 * 64 * 68 * 4;   // 52224 bytes
    cudaFuncSetAttribute(attn_kernel,
                         cudaFuncAttributeMaxDynamicSharedMemorySize, smem_attn);

    dim3 ggrid(ND / 64, NM / 64);   // (16, 64)
    gemm_xwT_kernel<<<ggrid, 256>>>(x, Wq, bq, (float*)pq);
    gemm_xwT_kernel<<<ggrid, 256>>>(x, Wk, bk, (float*)pk);
    gemm_xwT_kernel<<<ggrid, 256>>>(x, Wv, bv, (float*)pv);

    dim3 agrid(NS / 64, NB * NH);   // (32, 32)
    attn_kernel<<<agrid, 256, smem_attn>>>((const float*)pq, (const float*)pk,
                                           (const float*)pv, (float*)patt);

    gemm_xwT_kernel<<<ggrid, 256>>>((const float*)patt, Wf, bf, out);
}

// round 5
// speedup vs baseline: 1.7706x; 1.7706x over previous
#include <cuda_runtime.h>
#include <cstdint>

// Problem constants
constexpr int NB  = 2;
constexpr int NS  = 2048;
constexpr int ND  = 1024;
constexpr int NH  = 16;
constexpr int NHD = 64;
constexpr int NM  = NB * NS;          // 4096 rows

// Scratch (allocation-free rule: device globals)
__device__ float g_q[NM * ND];
__device__ float g_k[NM * ND];
__device__ float g_v[NM * ND];
__device__ float g_att[NM * ND];
__device__ float g_xr[NM * ND];       // tf32-rounded x
__device__ float g_wr[4][ND * ND];    // tf32-rounded Wq,Wk,Wv,Wf

// ---------------------------------------------------------------------------
// helpers
// ---------------------------------------------------------------------------
__device__ __forceinline__ float tf32r(float x) {
    uint32_t u;
    asm("cvt.rna.tf32.f32 %0, %1;" : "=r"(u) : "f"(x));
    return __uint_as_float(u);
}

__device__ __forceinline__ void cpasync16(uint32_t dst, const void* src) {
    asm volatile("cp.async.cg.shared.global [%0], [%1], 16;"
                 :: "r"(dst), "l"(src));
}
__device__ __forceinline__ void cp_commit() {
    asm volatile("cp.async.commit_group;");
}

__device__ __forceinline__ uint32_t smem_u32(const void* p) {
    uint32_t a;
    asm("{ .reg .u64 t; cvta.to.shared.u64 t, %1; cvt.u32.u64 %0, t; }"
        : "=r"(a) : "l"(p));
    return a;
}

// ---------------------------------------------------------------------------
// elementwise tf32 rounding pass
// ---------------------------------------------------------------------------
__global__ void round_kernel(const float4* __restrict__ s, float4* __restrict__ d, int n4) {
    int i = blockIdx.x * blockDim.x + threadIdx.x;
    if (i < n4) {
        float4 v = s[i];
        v.x = tf32r(v.x); v.y = tf32r(v.y); v.z = tf32r(v.z); v.w = tf32r(v.w);
        d[i] = v;
    }
}

// ---------------------------------------------------------------------------
// tf32 mma.sync GEMM: Y[M,N] = X[M,K] @ W[N,K]^T + bias
// M=4096, N=K=1024. CTA tile 128x128, BK=32, 3-stage cp.async pipeline.
// 8 warps, warp tile 32x64 (2 x 8 m16n8k8 fragments).
// Smem pitch 36 floats -> fragment LDS bank = (4r + c) mod 32, conflict-free.
// ---------------------------------------------------------------------------
constexpr int BM = 128, BN = 128, BK = 32, PITCH = 36;
constexpr int TILE_BYTES  = BM * PITCH * 4;      // 18432
constexpr int STAGE_BYTES = 2 * TILE_BYTES;      // 36864
constexpr int GEMM_SMEM   = 3 * STAGE_BYTES;     // 110592
constexpr int NCHUNK = ND / BK;                  // 32

__global__ __launch_bounds__(256) void gemm_tc(
    const float* __restrict__ X, const float* __restrict__ W,
    const float* __restrict__ bias, float* __restrict__ Y)
{
    extern __shared__ __align__(16) char dsm[];
    const int tid = threadIdx.x;
    const int m0 = blockIdx.y * BM, n0 = blockIdx.x * BN;
    const uint32_t sbase = smem_u32(dsm);

    auto load_stage = [&](int j) {
        const uint32_t sb = sbase + (j % 3) * STAGE_BYTES;
        const int k0 = j * BK;
        #pragma unroll
        for (int rr = 0; rr < 4; rr++) {             // A: 128 rows x 8 chunks
            int o = tid + 256 * rr;
            int row = o >> 3, ch = o & 7;
            cpasync16(sb + row * (PITCH * 4) + ch * 16,
                      X + (size_t)(m0 + row) * ND + k0 + ch * 4);
        }
        #pragma unroll
        for (int rr = 0; rr < 4; rr++) {             // B: 128 rows x 8 chunks
            int o = tid + 256 * rr;
            int row = o >> 3, ch = o & 7;
            cpasync16(sb + TILE_BYTES + row * (PITCH * 4) + ch * 16,
                      W + (size_t)(n0 + row) * ND + k0 + ch * 4);
        }
    };

    load_stage(0); cp_commit();
    load_stage(1); cp_commit();

    const int lane = tid & 31, w = tid >> 5;
    const int wm = (w & 3) * 32, wn = (w >> 2) * 64;
    const int r = lane >> 2, c = lane & 3;

    float acc[2][8][4];
    #pragma unroll
    for (int mi = 0; mi < 2; mi++)
        #pragma unroll
        for (int ni = 0; ni < 8; ni++)
            #pragma unroll
            for (int q = 0; q < 4; q++) acc[mi][ni][q] = 0.f;

    for (int chunk = 0; chunk < NCHUNK; chunk++) {
        asm volatile("cp.async.wait_group 1;" ::: "memory");
        __syncthreads();
        const uint32_t* As = (const uint32_t*)(dsm + (chunk % 3) * STAGE_BYTES);
        const uint32_t* Bs = (const uint32_t*)(dsm + (chunk % 3) * STAGE_BYTES + TILE_BYTES);

        #pragma unroll
        for (int kk = 0; kk < 4; kk++) {
            uint32_t a[2][4], b[8][2];
            #pragma unroll
            for (int mi = 0; mi < 2; mi++) {
                const int row = wm + mi * 16 + r;
                a[mi][0] = As[row * PITCH + kk * 8 + c];
                a[mi][1] = As[(row + 8) * PITCH + kk * 8 + c];
                a[mi][2] = As[row * PITCH + kk * 8 + c + 4];
                a[mi][3] = As[(row + 8) * PITCH + kk * 8 + c + 4];
            }
            #pragma unroll
            for (int ni = 0; ni < 8; ni++) {
                const int rowb = wn + ni * 8 + r;
                b[ni][0] = Bs[rowb * PITCH + kk * 8 + c];
                b[ni][1] = Bs[rowb * PITCH + kk * 8 + c + 4];
            }
            #pragma unroll
            for (int mi = 0; mi < 2; mi++)
                #pragma unroll
                for (int ni = 0; ni < 8; ni++)
                    asm volatile(
                        "mma.sync.aligned.m16n8k8.row.col.f32.tf32.tf32.f32 "
                        "{%0,%1,%2,%3}, {%4,%5,%6,%7}, {%8,%9}, {%0,%1,%2,%3};"
                        : "+f"(acc[mi][ni][0]), "+f"(acc[mi][ni][1]),
                          "+f"(acc[mi][ni][2]), "+f"(acc[mi][ni][3])
                        : "r"(a[mi][0]), "r"(a[mi][1]), "r"(a[mi][2]), "r"(a[mi][3]),
                          "r"(b[ni][0]), "r"(b[ni][1]));
        }
        __syncthreads();
        if (chunk + 2 < NCHUNK) load_stage(chunk + 2);
        cp_commit();
    }

    // Epilogue: c0,c1 -> (row, 2c..2c+1), c2,c3 -> (row+8, ...)
    #pragma unroll
    for (int ni = 0; ni < 8; ni++) {
        const int col = n0 + wn + ni * 8 + 2 * c;
        const float2 bv = *(const float2*)&bias[col];
        #pragma unroll
        for (int mi = 0; mi < 2; mi++) {
            const int gr = m0 + wm + mi * 16 + r;
            float2 o0 = make_float2(acc[mi][ni][0] + bv.x, acc[mi][ni][1] + bv.y);
            float2 o1 = make_float2(acc[mi][ni][2] + bv.x, acc[mi][ni][3] + bv.y);
            *(float2*)&Y[(size_t)gr * ND + col] = o0;
            *(float2*)&Y[(size_t)(gr + 8) * ND + col] = o1;
        }
    }
}

// ---------------------------------------------------------------------------
// Flash-style causal attention, fp32 (unchanged from passing R3 version;
// output tf32-rounded so the final projection consumes exact-tf32 inputs).
// ---------------------------------------------------------------------------
__global__ __launch_bounds__(256) void attn_kernel(
    const float* __restrict__ Q, const float* __restrict__ Kg,
    const float* __restrict__ V, float* __restrict__ O)
{
    extern __shared__ float sm[];
    float* QsT = sm;                 // [d][q-row], pitch 68
    float* KsT = sm + 64 * 68;       // [d][k-col], pitch 68; reused as P[q][k]
    float* Vs  = sm + 2 * 64 * 68;   // [k][d], pitch 68

    const int tid = threadIdx.x;
    const int ty = tid >> 4, tx = tid & 15;
    const int qt = blockIdx.x;
    const int bh = blockIdx.y;
    const int b = bh >> 4, h = bh & 15;
    const int q0 = qt * 64;
    const size_t rowbase = (size_t)b * NS;
    const int coff = h * NHD;

    const int lr = tid >> 2, lc4 = tid & 3;

    #pragma unroll
    for (int cc = 0; cc < 4; cc++) {
        const int c0 = 16 * cc + 4 * lc4;
        float4 qv = *(const float4*)&Q[(rowbase + q0 + lr) * ND + coff + c0];
        QsT[(c0 + 0) * 68 + lr] = qv.x;
        QsT[(c0 + 1) * 68 + lr] = qv.y;
        QsT[(c0 + 2) * 68 + lr] = qv.z;
        QsT[(c0 + 3) * 68 + lr] = qv.w;
    }

    float m_i[4], l_i[4];
    float acc[4][4] = {};
    #pragma unroll
    for (int i = 0; i < 4; i++) { m_i[i] = -1e30f; l_i[i] = 0.f; }

    __syncthreads();

    for (int kt = 0; kt <= qt; kt++) {
        const int k0 = kt * 64;
        float4 kv[4], vv[4];
        #pragma unroll
        for (int cc = 0; cc < 4; cc++) {
            const int c0 = 16 * cc + 4 * lc4;
            kv[cc] = *(const float4*)&Kg[(rowbase + k0 + lr) * ND + coff + c0];
            vv[cc] = *(const float4*)&V [(rowbase + k0 + lr) * ND + coff + c0];
        }
        __syncthreads();
        #pragma unroll
        for (int cc = 0; cc < 4; cc++) {
            const int c0 = 16 * cc + 4 * lc4;
            KsT[(c0 + 0) * 68 + lr] = kv[cc].x;
            KsT[(c0 + 1) * 68 + lr] = kv[cc].y;
            KsT[(c0 + 2) * 68 + lr] = kv[cc].z;
            KsT[(c0 + 3) * 68 + lr] = kv[cc].w;
            *(float4*)&Vs[lr * 68 + c0] = vv[cc];
        }
        __syncthreads();

        float sv[4][4] = {};
        #pragma unroll 8
        for (int d = 0; d < 64; d++) {
            float4 a = *(const float4*)&QsT[d * 68 + 4 * ty];
            float4 bq = *(const float4*)&KsT[d * 68 + 4 * tx];
            sv[0][0] += a.x * bq.x; sv[0][1] += a.x * bq.y; sv[0][2] += a.x * bq.z; sv[0][3] += a.x * bq.w;
            sv[1][0] += a.y * bq.x; sv[1][1] += a.y * bq.y; sv[1][2] += a.y * bq.z; sv[1][3] += a.y * bq.w;
            sv[2][0] += a.z * bq.x; sv[2][1] += a.z * bq.y; sv[2][2] += a.z * bq.z; sv[2][3] += a.z * bq.w;
            sv[3][0] += a.w * bq.x; sv[3][1] += a.w * bq.y; sv[3][2] += a.w * bq.z; sv[3][3] += a.w * bq.w;
        }

        const bool diag = (kt == qt);

        #pragma unroll
        for (int i = 0; i < 4; i++) {
            const int qrow = 4 * ty + i;
            float rowmax = -1e30f;
            #pragma unroll
            for (int j = 0; j < 4; j++) {
                float s = sv[i][j] * 0.125f;
                if (diag && (4 * tx + j) > qrow) s = -1e30f;
                sv[i][j] = s;
                rowmax = fmaxf(rowmax, s);
            }
            #pragma unroll
            for (int off = 8; off >= 1; off >>= 1)
                rowmax = fmaxf(rowmax, __shfl_xor_sync(0xffffffffu, rowmax, off));

            float mnew = fmaxf(m_i[i], rowmax);
            float corr = __expf(m_i[i] - mnew);
            float rs = 0.f;
            #pragma unroll
            for (int j = 0; j < 4; j++) {
                float p = __expf(sv[i][j] - mnew);
                sv[i][j] = p;
                rs += p;
            }
            #pragma unroll
            for (int off = 8; off >= 1; off >>= 1)
                rs += __shfl_xor_sync(0xffffffffu, rs, off);

            l_i[i] = l_i[i] * corr + rs;
            m_i[i] = mnew;
            #pragma unroll
            for (int j = 0; j < 4; j++) acc[i][j] *= corr;
        }

        __syncthreads();
        float* Ps = KsT;
        #pragma unroll
        for (int i = 0; i < 4; i++) {
            float4 p4 = make_float4(sv[i][0], sv[i][1], sv[i][2], sv[i][3]);
            *(float4*)&Ps[(4 * ty + i) * 68 + 4 * tx] = p4;
        }
        __syncthreads();

        #pragma unroll 8
        for (int kk = 0; kk < 64; kk++) {
            float4 v4 = *(const float4*)&Vs[kk * 68 + 4 * tx];
            float p0 = Ps[(4 * ty + 0) * 68 + kk];
            float p1 = Ps[(4 * ty + 1) * 68 + kk];
            float p2 = Ps[(4 * ty + 2) * 68 + kk];
            float p3 = Ps[(4 * ty + 3) * 68 + kk];
            acc[0][0] += p0 * v4.x; acc[0][1] += p0 * v4.y; acc[0][2] += p0 * v4.z; acc[0][3] += p0 * v4.w;
            acc[1][0] += p1 * v4.x; acc[1][1] += p1 * v4.y; acc[1][2] += p1 * v4.z; acc[1][3] += p1 * v4.w;
            acc[2][0] += p2 * v4.x; acc[2][1] += p2 * v4.y; acc[2][2] += p2 * v4.z; acc[2][3] += p2 * v4.w;
            acc[3][0] += p3 * v4.x; acc[3][1] += p3 * v4.y; acc[3][2] += p3 * v4.z; acc[3][3] += p3 * v4.w;
        }
    }

    #pragma unroll
    for (int i = 0; i < 4; i++) {
        float inv = 1.f / l_i[i];
        float4 o = make_float4(tf32r(acc[i][0] * inv), tf32r(acc[i][1] * inv),
                               tf32r(acc[i][2] * inv), tf32r(acc[i][3] * inv));
        *(float4*)&O[(rowbase + q0 + 4 * ty + i) * ND + coff + 4 * tx] = o;
    }
}

// ---------------------------------------------------------------------------
extern "C" void kernel_launch(void* const* d_in, const int* in_sizes, int n_in,
                              void* d_out, int out_size)
{
    const float* x  = (const float*)d_in[0];
    const float* Wq = (const float*)d_in[1];
    const float* bq = (const float*)d_in[2];
    const float* Wk = (const float*)d_in[3];
    const float* bk = (const float*)d_in[4];
    const float* Wv = (const float*)d_in[5];
    const float* bv = (const float*)d_in[6];
    const float* Wf = (const float*)d_in[7];
    const float* bf = (const float*)d_in[8];
    float* out = (float*)d_out;

    void *pq, *pk, *pv, *patt, *pxr, *pwr;
    cudaGetSymbolAddress(&pq,   g_q);
    cudaGetSymbolAddress(&pk,   g_k);
    cudaGetSymbolAddress(&pv,   g_v);
    cudaGetSymbolAddress(&patt, g_att);
    cudaGetSymbolAddress(&pxr,  g_xr);
    cudaGetSymbolAddress(&pwr,  g_wr);
    float* xr = (float*)pxr;
    float* wr = (float*)pwr;   // [4][ND*ND]

    const int smem_attn = 3 * 64 * 68 * 4;
    cudaFuncSetAttribute(attn_kernel,
                         cudaFuncAttributeMaxDynamicSharedMemorySize, smem_attn);
    cudaFuncSetAttribute(gemm_tc,
                         cudaFuncAttributeMaxDynamicSharedMemorySize, GEMM_SMEM);

    // tf32-round inputs
    const int n4x = NM * ND / 4;       // 1,048,576
    const int n4w = ND * ND / 4;       // 262,144
    round_kernel<<<n4x / 256, 256>>>((const float4*)x,  (float4*)xr, n4x);
    round_kernel<<<n4w / 256, 256>>>((const float4*)Wq, (float4*)(wr + 0 * ND * ND), n4w);
    round_kernel<<<n4w / 256, 256>>>((const float4*)Wk, (float4*)(wr + 1 * ND * ND), n4w);
    round_kernel<<<n4w / 256, 256>>>((const float4*)Wv, (float4*)(wr + 2 * ND * ND), n4w);
    round_kernel<<<n4w / 256, 256>>>((const float4*)Wf, (float4*)(wr + 3 * ND * ND), n4w);

    dim3 ggrid(ND / BN, NM / BM);      // (8, 32) = 256 CTAs
    gemm_tc<<<ggrid, 256, GEMM_SMEM>>>(xr, wr + 0 * ND * ND, bq, (float*)pq);
    gemm_tc<<<ggrid, 256, GEMM_SMEM>>>(xr, wr + 1 * ND * ND, bk, (float*)pk);
    gemm_tc<<<ggrid, 256, GEMM_SMEM>>>(xr, wr + 2 * ND * ND, bv, (float*)pv);

    dim3 agrid(NS / 64, NB * NH);      // (32, 32)
    attn_kernel<<<agrid, 256, smem_attn>>>((const float*)pq, (const float*)pk,
                                           (const float*)pv, (float*)patt);

    gemm_tc<<<ggrid, 256, GEMM_SMEM>>>((const float*)patt, wr + 3 * ND * ND, bf, out);
}

// round 6
// speedup vs baseline: 3.0283x; 1.7103x over previous
#include <cuda_runtime.h>
#include <cstdint>

// Problem constants
constexpr int NB  = 2;
constexpr int NS  = 2048;
constexpr int ND  = 1024;
constexpr int NH  = 16;
constexpr int NHD = 64;
constexpr int NM  = NB * NS;          // 4096 rows

// Scratch (allocation-free rule: device globals)
__device__ float g_q[NM * ND];
__device__ float g_k[NM * ND];
__device__ float g_v[NM * ND];
__device__ float g_att[NM * ND];
__device__ float g_xr[NM * ND];       // tf32-rounded x
__device__ float g_wr[4][ND * ND];    // tf32-rounded Wq,Wk,Wv,Wf

// ---------------------------------------------------------------------------
// helpers
// ---------------------------------------------------------------------------
__device__ __forceinline__ float tf32r(float x) {
    uint32_t u;
    asm("cvt.rna.tf32.f32 %0, %1;" : "=r"(u) : "f"(x));
    return __uint_as_float(u);
}

__device__ __forceinline__ void cpasync16(uint32_t dst, const void* src) {
    asm volatile("cp.async.cg.shared.global [%0], [%1], 16;"
                 :: "r"(dst), "l"(src));
}
__device__ __forceinline__ void cp_commit() {
    asm volatile("cp.async.commit_group;");
}

__device__ __forceinline__ uint32_t smem_u32(const void* p) {
    uint32_t a;
    asm("{ .reg .u64 t; cvta.to.shared.u64 t, %1; cvt.u32.u64 %0, t; }"
        : "=r"(a) : "l"(p));
    return a;
}

__device__ __forceinline__ void mma_tf32(float* d, uint32_t a0, uint32_t a1,
                                         uint32_t a2, uint32_t a3,
                                         uint32_t b0, uint32_t b1) {
    asm volatile(
        "mma.sync.aligned.m16n8k8.row.col.f32.tf32.tf32.f32 "
        "{%0,%1,%2,%3}, {%4,%5,%6,%7}, {%8,%9}, {%0,%1,%2,%3};"
        : "+f"(d[0]), "+f"(d[1]), "+f"(d[2]), "+f"(d[3])
        : "r"(a0), "r"(a1), "r"(a2), "r"(a3), "r"(b0), "r"(b1));
}

// ---------------------------------------------------------------------------
// elementwise tf32 rounding pass
// ---------------------------------------------------------------------------
__global__ void round_kernel(const float4* __restrict__ s, float4* __restrict__ d, int n4) {
    int i = blockIdx.x * blockDim.x + threadIdx.x;
    if (i < n4) {
        float4 v = s[i];
        v.x = tf32r(v.x); v.y = tf32r(v.y); v.z = tf32r(v.z); v.w = tf32r(v.w);
        d[i] = v;
    }
}

// ---------------------------------------------------------------------------
// tf32 mma.sync GEMM: Y[M,N] = X[M,K] @ W[N,K]^T + bias
// ROUND: tf32-round the output (for Q/K/V so attention consumes exact tf32).
// ---------------------------------------------------------------------------
constexpr int BM = 128, BN = 128, BK = 32, PITCH = 36;
constexpr int TILE_BYTES  = BM * PITCH * 4;      // 18432
constexpr int STAGE_BYTES = 2 * TILE_BYTES;      // 36864
constexpr int GEMM_SMEM   = 3 * STAGE_BYTES;     // 110592
constexpr int NCHUNK = ND / BK;                  // 32

template<bool ROUND>
__global__ __launch_bounds__(256) void gemm_tc(
    const float* __restrict__ X, const float* __restrict__ W,
    const float* __restrict__ bias, float* __restrict__ Y)
{
    extern __shared__ __align__(16) char dsm[];
    const int tid = threadIdx.x;
    const int m0 = blockIdx.y * BM, n0 = blockIdx.x * BN;
    const uint32_t sbase = smem_u32(dsm);

    auto load_stage = [&](int j) {
        const uint32_t sb = sbase + (j % 3) * STAGE_BYTES;
        const int k0 = j * BK;
        #pragma unroll
        for (int rr = 0; rr < 4; rr++) {
            int o = tid + 256 * rr;
            int row = o >> 3, ch = o & 7;
            cpasync16(sb + row * (PITCH * 4) + ch * 16,
                      X + (size_t)(m0 + row) * ND + k0 + ch * 4);
        }
        #pragma unroll
        for (int rr = 0; rr < 4; rr++) {
            int o = tid + 256 * rr;
            int row = o >> 3, ch = o & 7;
            cpasync16(sb + TILE_BYTES + row * (PITCH * 4) + ch * 16,
                      W + (size_t)(n0 + row) * ND + k0 + ch * 4);
        }
    };

    load_stage(0); cp_commit();
    load_stage(1); cp_commit();

    const int lane = tid & 31, w = tid >> 5;
    const int wm = (w & 3) * 32, wn = (w >> 2) * 64;
    const int r = lane >> 2, c = lane & 3;

    float acc[2][8][4];
    #pragma unroll
    for (int mi = 0; mi < 2; mi++)
        #pragma unroll
        for (int ni = 0; ni < 8; ni++)
            #pragma unroll
            for (int q = 0; q < 4; q++) acc[mi][ni][q] = 0.f;

    for (int chunk = 0; chunk < NCHUNK; chunk++) {
        asm volatile("cp.async.wait_group 1;" ::: "memory");
        __syncthreads();
        const uint32_t* As = (const uint32_t*)(dsm + (chunk % 3) * STAGE_BYTES);
        const uint32_t* Bs = (const uint32_t*)(dsm + (chunk % 3) * STAGE_BYTES + TILE_BYTES);

        #pragma unroll
        for (int kk = 0; kk < 4; kk++) {
            uint32_t a[2][4], b[8][2];
            #pragma unroll
            for (int mi = 0; mi < 2; mi++) {
                const int row = wm + mi * 16 + r;
                a[mi][0] = As[row * PITCH + kk * 8 + c];
                a[mi][1] = As[(row + 8) * PITCH + kk * 8 + c];
                a[mi][2] = As[row * PITCH + kk * 8 + c + 4];
                a[mi][3] = As[(row + 8) * PITCH + kk * 8 + c + 4];
            }
            #pragma unroll
            for (int ni = 0; ni < 8; ni++) {
                const int rowb = wn + ni * 8 + r;
                b[ni][0] = Bs[rowb * PITCH + kk * 8 + c];
                b[ni][1] = Bs[rowb * PITCH + kk * 8 + c + 4];
            }
            #pragma unroll
            for (int mi = 0; mi < 2; mi++)
                #pragma unroll
                for (int ni = 0; ni < 8; ni++)
                    mma_tf32(acc[mi][ni], a[mi][0], a[mi][1], a[mi][2], a[mi][3],
                             b[ni][0], b[ni][1]);
        }
        __syncthreads();
        if (chunk + 2 < NCHUNK) load_stage(chunk + 2);
        cp_commit();
    }

    #pragma unroll
    for (int ni = 0; ni < 8; ni++) {
        const int col = n0 + wn + ni * 8 + 2 * c;
        const float2 bv = *(const float2*)&bias[col];
        #pragma unroll
        for (int mi = 0; mi < 2; mi++) {
            const int gr = m0 + wm + mi * 16 + r;
            float2 o0, o1;
            if (ROUND) {
                o0 = make_float2(tf32r(acc[mi][ni][0] + bv.x), tf32r(acc[mi][ni][1] + bv.y));
                o1 = make_float2(tf32r(acc[mi][ni][2] + bv.x), tf32r(acc[mi][ni][3] + bv.y));
            } else {
                o0 = make_float2(acc[mi][ni][0] + bv.x, acc[mi][ni][1] + bv.y);
                o1 = make_float2(acc[mi][ni][2] + bv.x, acc[mi][ni][3] + bv.y);
            }
            *(float2*)&Y[(size_t)gr * ND + col] = o0;
            *(float2*)&Y[(size_t)(gr + 8) * ND + col] = o1;
        }
    }
}

// ---------------------------------------------------------------------------
// Flash attention with tf32 mma.sync.
// Block: 256 threads (8 warps), 128 q-rows per block, one (b,h) per blockIdx.y.
// Warp w owns q-rows [w*16, w*16+16). K-tiles of 64; iters = 2*(qt+1).
// Smem (pitch 68 floats): Qs[128] | Ks[64] | Vt[64] (dim-major) | Ps[128].
// Inputs Q/K/V are exact tf32 values (rounded at projection epilogue);
// P is tf32-rounded before mma2 and l sums the rounded p -> mma ops are exact.
// ---------------------------------------------------------------------------
constexpr int AP = 68;
constexpr int ATTN_SMEM = 384 * AP * 4;   // 104448 bytes

__global__ __launch_bounds__(256, 2) void attn_tc(
    const float* __restrict__ Q, const float* __restrict__ Kg,
    const float* __restrict__ V, float* __restrict__ O)
{
    extern __shared__ float sm[];
    float* Qs = sm;                    // [q-row 128][AP]
    float* Ks = sm + 128 * AP;         // [key 64][AP]  (dim-major per key row)
    float* Vt = sm + 192 * AP;         // [dim 64][AP]  (key-major per dim row)
    float* Ps = sm + 256 * AP;         // [q-row 128][AP]

    const int tid = threadIdx.x;
    const int lane = tid & 31, w = tid >> 5;
    const int r = lane >> 2, c = lane & 3;
    const int wm = w * 16;

    const int qt = (int)gridDim.x - 1 - (int)blockIdx.x;   // heavy tiles first
    const int q0 = qt * 128;
    const int bh = blockIdx.y;
    const int b = bh >> 4, h = bh & 15;
    const size_t rowbase = (size_t)b * NS;
    const int coff = h * NHD;

    // Load Q tile once, pre-scaled by exact 0.125 (1/sqrt(64))
    #pragma unroll
    for (int i = 0; i < 8; i++) {
        int o = tid + 256 * i;
        int row = o >> 4, c4 = (o & 15) * 4;
        float4 qv = *(const float4*)&Q[(rowbase + q0 + row) * ND + coff + c4];
        qv.x *= 0.125f; qv.y *= 0.125f; qv.z *= 0.125f; qv.w *= 0.125f;
        *(float4*)&Qs[row * AP + c4] = qv;
    }

    float m0v = -1e30f, m1v = -1e30f, l0 = 0.f, l1 = 0.f;
    float oacc[8][4];
    #pragma unroll
    for (int ni = 0; ni < 8; ni++)
        #pragma unroll
        for (int q = 0; q < 4; q++) oacc[ni][q] = 0.f;

    const int row0 = q0 + wm + r, row1 = row0 + 8;
    const int kiters = 2 * (qt + 1);

    for (int it = 0; it < kiters; it++) {
        const int k0 = it * 64;
        // prefetch K/V tile into regs (4 float4 each per thread)
        float4 kv[4], vv[4];
        #pragma unroll
        for (int i = 0; i < 4; i++) {
            int o = tid + 256 * i;
            int row = o >> 4, c4 = (o & 15) * 4;
            kv[i] = *(const float4*)&Kg[(rowbase + k0 + row) * ND + coff + c4];
            vv[i] = *(const float4*)&V [(rowbase + k0 + row) * ND + coff + c4];
        }
        __syncthreads();   // prior iteration's mma reads of Ks/Vt complete
        #pragma unroll
        for (int i = 0; i < 4; i++) {
            int o = tid + 256 * i;
            int row = o >> 4, c4 = (o & 15) * 4;
            *(float4*)&Ks[row * AP + c4] = kv[i];
            Vt[(c4 + 0) * AP + row] = vv[i].x;
            Vt[(c4 + 1) * AP + row] = vv[i].y;
            Vt[(c4 + 2) * AP + row] = vv[i].z;
            Vt[(c4 + 3) * AP + row] = vv[i].w;
        }
        __syncthreads();

        // ---- S[16 x 64] = Qtile @ Ktile^T (scaled) ----
        float sacc[8][4];
        #pragma unroll
        for (int ni = 0; ni < 8; ni++)
            #pragma unroll
            for (int q = 0; q < 4; q++) sacc[ni][q] = 0.f;

        const uint32_t* Qu = (const uint32_t*)Qs;
        const uint32_t* Ku = (const uint32_t*)Ks;
        #pragma unroll
        for (int kk = 0; kk < 8; kk++) {
            uint32_t a0 = Qu[(wm + r) * AP + kk * 8 + c];
            uint32_t a1 = Qu[(wm + r + 8) * AP + kk * 8 + c];
            uint32_t a2 = Qu[(wm + r) * AP + kk * 8 + c + 4];
            uint32_t a3 = Qu[(wm + r + 8) * AP + kk * 8 + c + 4];
            #pragma unroll
            for (int ni = 0; ni < 8; ni++) {
                uint32_t b0 = Ku[(ni * 8 + r) * AP + kk * 8 + c];
                uint32_t b1 = Ku[(ni * 8 + r) * AP + kk * 8 + c + 4];
                mma_tf32(sacc[ni], a0, a1, a2, a3, b0, b1);
            }
        }

        // ---- causal mask (only near diagonal) ----
        if (k0 + 63 > row0) {
            #pragma unroll
            for (int ni = 0; ni < 8; ni++) {
                const int col = k0 + ni * 8 + 2 * c;
                if (col > row0)     sacc[ni][0] = -1e30f;
                if (col + 1 > row0) sacc[ni][1] = -1e30f;
                if (col > row1)     sacc[ni][2] = -1e30f;
                if (col + 1 > row1) sacc[ni][3] = -1e30f;
            }
        }

        // ---- online softmax (rows row0, row1; reduce over 4 lanes) ----
        float rm0 = -1e30f, rm1 = -1e30f;
        #pragma unroll
        for (int ni = 0; ni < 8; ni++) {
            rm0 = fmaxf(rm0, fmaxf(sacc[ni][0], sacc[ni][1]));
            rm1 = fmaxf(rm1, fmaxf(sacc[ni][2], sacc[ni][3]));
        }
        rm0 = fmaxf(rm0, __shfl_xor_sync(0xffffffffu, rm0, 1));
        rm0 = fmaxf(rm0, __shfl_xor_sync(0xffffffffu, rm0, 2));
        rm1 = fmaxf(rm1, __shfl_xor_sync(0xffffffffu, rm1, 1));
        rm1 = fmaxf(rm1, __shfl_xor_sync(0xffffffffu, rm1, 2));

        const float mn0 = fmaxf(m0v, rm0), mn1 = fmaxf(m1v, rm1);
        const float corr0 = __expf(m0v - mn0), corr1 = __expf(m1v - mn1);
        float rs0 = 0.f, rs1 = 0.f;
        #pragma unroll
        for (int ni = 0; ni < 8; ni++) {
            float p0 = tf32r(__expf(sacc[ni][0] - mn0));
            float p1 = tf32r(__expf(sacc[ni][1] - mn0));
            float p2 = tf32r(__expf(sacc[ni][2] - mn1));
            float p3 = tf32r(__expf(sacc[ni][3] - mn1));
            sacc[ni][0] = p0; sacc[ni][1] = p1; sacc[ni][2] = p2; sacc[ni][3] = p3;
            rs0 += p0 + p1; rs1 += p2 + p3;
        }
        rs0 += __shfl_xor_sync(0xffffffffu, rs0, 1);
        rs0 += __shfl_xor_sync(0xffffffffu, rs0, 2);
        rs1 += __shfl_xor_sync(0xffffffffu, rs1, 1);
        rs1 += __shfl_xor_sync(0xffffffffu, rs1, 2);

        l0 = l0 * corr0 + rs0;  m0v = mn0;
        l1 = l1 * corr1 + rs1;  m1v = mn1;
        #pragma unroll
        for (int ni = 0; ni < 8; ni++) {
            oacc[ni][0] *= corr0; oacc[ni][1] *= corr0;
            oacc[ni][2] *= corr1; oacc[ni][3] *= corr1;
        }

        // ---- write P (warp-private rows) ----
        #pragma unroll
        for (int ni = 0; ni < 8; ni++) {
            *(float2*)&Ps[(wm + r) * AP + ni * 8 + 2 * c] =
                make_float2(sacc[ni][0], sacc[ni][1]);
            *(float2*)&Ps[(wm + r + 8) * AP + ni * 8 + 2 * c] =
                make_float2(sacc[ni][2], sacc[ni][3]);
        }
        __syncwarp();

        // ---- O[16 x 64] += P @ V ----
        const uint32_t* Pu = (const uint32_t*)Ps;
        const uint32_t* Vu = (const uint32_t*)Vt;
        #pragma unroll
        for (int kk = 0; kk < 8; kk++) {
            uint32_t a0 = Pu[(wm + r) * AP + kk * 8 + c];
            uint32_t a1 = Pu[(wm + r + 8) * AP + kk * 8 + c];
            uint32_t a2 = Pu[(wm + r) * AP + kk * 8 + c + 4];
            uint32_t a3 = Pu[(wm + r + 8) * AP + kk * 8 + c + 4];
            #pragma unroll
            for (int ni = 0; ni < 8; ni++) {
                uint32_t b0 = Vu[(ni * 8 + r) * AP + kk * 8 + c];
                uint32_t b1 = Vu[(ni * 8 + r) * AP + kk * 8 + c + 4];
                mma_tf32(oacc[ni], a0, a1, a2, a3, b0, b1);
            }
        }
    }

    // ---- epilogue: normalize, tf32-round (final GEMM input), store ----
    const float inv0 = 1.f / l0, inv1 = 1.f / l1;
    #pragma unroll
    for (int ni = 0; ni < 8; ni++) {
        const int col = coff + ni * 8 + 2 * c;
        *(float2*)&O[(rowbase + row0) * ND + col] =
            make_float2(tf32r(oacc[ni][0] * inv0), tf32r(oacc[ni][1] * inv0));
        *(float2*)&O[(rowbase + row1) * ND + col] =
            make_float2(tf32r(oacc[ni][2] * inv1), tf32r(oacc[ni][3] * inv1));
    }
}

// ---------------------------------------------------------------------------
extern "C" void kernel_launch(void* const* d_in, const int* in_sizes, int n_in,
                              void* d_out, int out_size)
{
    const float* x  = (const float*)d_in[0];
    const float* Wq = (const float*)d_in[1];
    const float* bq = (const float*)d_in[2];
    const float* Wk = (const float*)d_in[3];
    const float* bk = (const float*)d_in[4];
    const float* Wv = (const float*)d_in[5];
    const float* bv = (const float*)d_in[6];
    const float* Wf = (const float*)d_in[7];
    const float* bf = (const float*)d_in[8];
    float* out = (float*)d_out;

    void *pq, *pk, *pv, *patt, *pxr, *pwr;
    cudaGetSymbolAddress(&pq,   g_q);
    cudaGetSymbolAddress(&pk,   g_k);
    cudaGetSymbolAddress(&pv,   g_v);
    cudaGetSymbolAddress(&patt, g_att);
    cudaGetSymbolAddress(&pxr,  g_xr);
    cudaGetSymbolAddress(&pwr,  g_wr);
    float* xr = (float*)pxr;
    float* wr = (float*)pwr;   // [4][ND*ND]

    cudaFuncSetAttribute(gemm_tc<true>,
                         cudaFuncAttributeMaxDynamicSharedMemorySize, GEMM_SMEM);
    cudaFuncSetAttribute(gemm_tc<false>,
                         cudaFuncAttributeMaxDynamicSharedMemorySize, GEMM_SMEM);
    cudaFuncSetAttribute(attn_tc,
                         cudaFuncAttributeMaxDynamicSharedMemorySize, ATTN_SMEM);

    // tf32-round GEMM inputs
    const int n4x = NM * ND / 4;
    const int n4w = ND * ND / 4;
    round_kernel<<<n4x / 256, 256>>>((const float4*)x,  (float4*)xr, n4x);
    round_kernel<<<n4w / 256, 256>>>((const float4*)Wq, (float4*)(wr + 0 * ND * ND), n4w);
    round_kernel<<<n4w / 256, 256>>>((const float4*)Wk, (float4*)(wr + 1 * ND * ND), n4w);
    round_kernel<<<n4w / 256, 256>>>((const float4*)Wv, (float4*)(wr + 2 * ND * ND), n4w);
    round_kernel<<<n4w / 256, 256>>>((const float4*)Wf, (float4*)(wr + 3 * ND * ND), n4w);

    dim3 ggrid(ND / BN, NM / BM);      // (8, 32)
    gemm_tc<true><<<ggrid, 256, GEMM_SMEM>>>(xr, wr + 0 * ND * ND, bq, (float*)pq);
    gemm_tc<true><<<ggrid, 256, GEMM_SMEM>>>(xr, wr + 1 * ND * ND, bk, (float*)pk);
    gemm_tc<true><<<ggrid, 256, GEMM_SMEM>>>(xr, wr + 2 * ND * ND, bv, (float*)pv);

    dim3 agrid(NS / 128, NB * NH);     // (16, 32)
    attn_tc<<<agrid, 256, ATTN_SMEM>>>((const float*)pq, (const float*)pk,
                                       (const float*)pv, (float*)patt);

    gemm_tc<false><<<ggrid, 256, GEMM_SMEM>>>((const float*)patt, wr + 3 * ND * ND, bf, out);
}

// round 9
// speedup vs baseline: 3.3021x; 1.0904x over previous
#include <cuda_runtime.h>
#include <cstdint>

// Problem constants
constexpr int NB  = 2;
constexpr int NS  = 2048;
constexpr int ND  = 1024;
constexpr int NH  = 16;
constexpr int NHD = 64;
constexpr int NM  = NB * NS;          // 4096 rows

// Scratch (allocation-free rule: device globals)
__device__ float g_q[NM * ND];
__device__ float g_k[NM * ND];
__device__ float g_v[NM * ND];
__device__ float g_att[NM * ND];
__device__ float g_xr[NM * ND];       // tf32-rounded x
__device__ float g_wr[4][ND * ND];    // tf32-rounded Wq,Wk,Wv,Wf

// ---------------------------------------------------------------------------
// helpers
// ---------------------------------------------------------------------------
__device__ __forceinline__ float tf32r(float x) {
    uint32_t u;
    asm("cvt.rna.tf32.f32 %0, %1;" : "=r"(u) : "f"(x));
    return __uint_as_float(u);
}

__device__ __forceinline__ void cpasync16(uint32_t dst, const void* src) {
    asm volatile("cp.async.cg.shared.global [%0], [%1], 16;"
                 :: "r"(dst), "l"(src));
}
__device__ __forceinline__ void cp_commit() {
    asm volatile("cp.async.commit_group;");
}

__device__ __forceinline__ uint32_t smem_u32(const void* p) {
    uint32_t a;
    asm("{ .reg .u64 t; cvta.to.shared.u64 t, %1; cvt.u32.u64 %0, t; }"
        : "=r"(a) : "l"(p));
    return a;
}

__device__ __forceinline__ void mma_tf32(float* d, uint32_t a0, uint32_t a1,
                                         uint32_t a2, uint32_t a3,
                                         uint32_t b0, uint32_t b1) {
    asm volatile(
        "mma.sync.aligned.m16n8k8.row.col.f32.tf32.tf32.f32 "
        "{%0,%1,%2,%3}, {%4,%5,%6,%7}, {%8,%9}, {%0,%1,%2,%3};"
        : "+f"(d[0]), "+f"(d[1]), "+f"(d[2]), "+f"(d[3])
        : "r"(a0), "r"(a1), "r"(a2), "r"(a3), "r"(b0), "r"(b1));
}

// ---------------------------------------------------------------------------
// elementwise tf32 rounding pass
// ---------------------------------------------------------------------------
__global__ void round_kernel(const float4* __restrict__ s, float4* __restrict__ d, int n4) {
    int i = blockIdx.x * blockDim.x + threadIdx.x;
    if (i < n4) {
        float4 v = s[i];
        v.x = tf32r(v.x); v.y = tf32r(v.y); v.z = tf32r(v.z); v.w = tf32r(v.w);
        d[i] = v;
    }
}

// ---------------------------------------------------------------------------
// tf32 mma.sync GEMM core (device inline): Y = X @ W^T + bias
// ---------------------------------------------------------------------------
constexpr int BM = 128, BN = 128, BK = 32, PITCH = 36;
constexpr int TILE_BYTES  = BM * PITCH * 4;      // 18432
constexpr int STAGE_BYTES = 2 * TILE_BYTES;      // 36864
constexpr int GEMM_SMEM   = 3 * STAGE_BYTES;     // 110592
constexpr int NCHUNK = ND / BK;                  // 32

template<bool ROUND>
__device__ __forceinline__ void gemm_body(
    char* dsm, const float* __restrict__ X, const float* __restrict__ W,
    const float* __restrict__ bias, float* __restrict__ Y, int m0, int n0)
{
    const int tid = threadIdx.x;
    const uint32_t sbase = smem_u32(dsm);

    auto load_stage = [&](int j) {
        const uint32_t sb = sbase + (j % 3) * STAGE_BYTES;
        const int k0 = j * BK;
        #pragma unroll
        for (int rr = 0; rr < 4; rr++) {
            int o = tid + 256 * rr;
            int row = o >> 3, ch = o & 7;
            cpasync16(sb + row * (PITCH * 4) + ch * 16,
                      X + (size_t)(m0 + row) * ND + k0 + ch * 4);
        }
        #pragma unroll
        for (int rr = 0; rr < 4; rr++) {
            int o = tid + 256 * rr;
            int row = o >> 3, ch = o & 7;
            cpasync16(sb + TILE_BYTES + row * (PITCH * 4) + ch * 16,
                      W + (size_t)(n0 + row) * ND + k0 + ch * 4);
        }
    };

    load_stage(0); cp_commit();
    load_stage(1); cp_commit();

    const int lane = tid & 31, w = tid >> 5;
    const int wm = (w & 3) * 32, wn = (w >> 2) * 64;
    const int r = lane >> 2, c = lane & 3;

    float acc[2][8][4];
    #pragma unroll
    for (int mi = 0; mi < 2; mi++)
        #pragma unroll
        for (int ni = 0; ni < 8; ni++)
            #pragma unroll
            for (int q = 0; q < 4; q++) acc[mi][ni][q] = 0.f;

    for (int chunk = 0; chunk < NCHUNK; chunk++) {
        asm volatile("cp.async.wait_group 1;" ::: "memory");
        __syncthreads();
        const uint32_t* As = (const uint32_t*)(dsm + (chunk % 3) * STAGE_BYTES);
        const uint32_t* Bs = (const uint32_t*)(dsm + (chunk % 3) * STAGE_BYTES + TILE_BYTES);

        #pragma unroll
        for (int kk = 0; kk < 4; kk++) {
            uint32_t a[2][4], b[8][2];
            #pragma unroll
            for (int mi = 0; mi < 2; mi++) {
                const int row = wm + mi * 16 + r;
                a[mi][0] = As[row * PITCH + kk * 8 + c];
                a[mi][1] = As[(row + 8) * PITCH + kk * 8 + c];
                a[mi][2] = As[row * PITCH + kk * 8 + c + 4];
                a[mi][3] = As[(row + 8) * PITCH + kk * 8 + c + 4];
            }
            #pragma unroll
            for (int ni = 0; ni < 8; ni++) {
                const int rowb = wn + ni * 8 + r;
                b[ni][0] = Bs[rowb * PITCH + kk * 8 + c];
                b[ni][1] = Bs[rowb * PITCH + kk * 8 + c + 4];
            }
            #pragma unroll
            for (int mi = 0; mi < 2; mi++)
                #pragma unroll
                for (int ni = 0; ni < 8; ni++)
                    mma_tf32(acc[mi][ni], a[mi][0], a[mi][1], a[mi][2], a[mi][3],
                             b[ni][0], b[ni][1]);
        }
        __syncthreads();
        if (chunk + 2 < NCHUNK) load_stage(chunk + 2);
        cp_commit();
    }

    #pragma unroll
    for (int ni = 0; ni < 8; ni++) {
        const int col = n0 + wn + ni * 8 + 2 * c;
        const float2 bv = *(const float2*)&bias[col];
        #pragma unroll
        for (int mi = 0; mi < 2; mi++) {
            const int gr = m0 + wm + mi * 16 + r;
            float2 o0, o1;
            if (ROUND) {
                o0 = make_float2(tf32r(acc[mi][ni][0] + bv.x), tf32r(acc[mi][ni][1] + bv.y));
                o1 = make_float2(tf32r(acc[mi][ni][2] + bv.x), tf32r(acc[mi][ni][3] + bv.y));
            } else {
                o0 = make_float2(acc[mi][ni][0] + bv.x, acc[mi][ni][1] + bv.y);
                o1 = make_float2(acc[mi][ni][2] + bv.x, acc[mi][ni][3] + bv.y);
            }
            *(float2*)&Y[(size_t)gr * ND + col] = o0;
            *(float2*)&Y[(size_t)(gr + 8) * ND + col] = o1;
        }
    }
}

// Fused Q/K/V projection: blockIdx.z selects the weight/bias/output triple.
__global__ __launch_bounds__(256) void gemm_qkv(
    const float* __restrict__ X,
    const float* __restrict__ W0, const float* __restrict__ W1, const float* __restrict__ W2,
    const float* __restrict__ b0, const float* __restrict__ b1, const float* __restrict__ b2,
    float* __restrict__ Y0, float* __restrict__ Y1, float* __restrict__ Y2)
{
    extern __shared__ __align__(16) char dsm[];
    const float* W = (blockIdx.z == 0) ? W0 : (blockIdx.z == 1) ? W1 : W2;
    const float* bb = (blockIdx.z == 0) ? b0 : (blockIdx.z == 1) ? b1 : b2;
    float* Y = (blockIdx.z == 0) ? Y0 : (blockIdx.z == 1) ? Y1 : Y2;
    gemm_body<true>(dsm, X, W, bb, Y, blockIdx.y * BM, blockIdx.x * BN);
}

__global__ __launch_bounds__(256) void gemm_out(
    const float* __restrict__ X, const float* __restrict__ W,
    const float* __restrict__ bias, float* __restrict__ Y)
{
    extern __shared__ __align__(16) char dsm[];
    gemm_body<false>(dsm, X, W, bias, Y, blockIdx.y * BM, blockIdx.x * BN);
}

// ---------------------------------------------------------------------------
// Flash attention, tf32 mma.sync, cp.async 2-stage K/V pipeline.
// Block: 256 threads (8 warps), 128 q-rows, one (b,h) per blockIdx.y.
// Warp w owns q-rows [w*16, w*16+16). K-tiles of 64 keys; iters = 2*(qt+1).
// Smem (pitch 68): Qs[128] | K stages 2x[64] | V stages 2x[64], all natural
// layout. S-mma B reads K rows (bank 4r+c, conflict-free). O-mma B reads V
// COLUMNS (bank (4c+r) mod 32, conflict-free) -> no V transpose. P never
// touches smem: S-fragments are re-distributed to O-mma A-fragments with
// intra-warp shuffles.
// ---------------------------------------------------------------------------
constexpr int AP = 68;
constexpr int ATTN_SMEM = 384 * AP * 4;   // 104448 bytes

__global__ __launch_bounds__(256, 2) void attn_tc(
    const float* __restrict__ Q, const float* __restrict__ Kg,
    const float* __restrict__ V, float* __restrict__ O)
{
    extern __shared__ float sm[];
    float* Qs = sm;                          // rows [0,128)
    // K stage s: rows [128 + 64s, ...), V stage s: rows [256 + 64s, ...)
    const uint32_t sb = smem_u32(sm);

    const int tid = threadIdx.x;
    const int lane = tid & 31, w = tid >> 5;
    const int r = lane >> 2, c = lane & 3;
    const int wm = w * 16;

    const int qt = (int)gridDim.x - 1 - (int)blockIdx.x;   // heavy tiles first
    const int q0 = qt * 128;
    const int bh = blockIdx.y;
    const int b = bh >> 4, h = bh & 15;
    const size_t rowbase = (size_t)b * NS;
    const int coff = h * NHD;

    // Load Q tile once, pre-scaled by exact 0.125 (1/sqrt(64))
    #pragma unroll
    for (int i = 0; i < 8; i++) {
        int o = tid + 256 * i;
        int row = o >> 4, c4 = (o & 15) * 4;
        float4 qv = *(const float4*)&Q[(rowbase + q0 + row) * ND + coff + c4];
        qv.x *= 0.125f; qv.y *= 0.125f; qv.z *= 0.125f; qv.w *= 0.125f;
        *(float4*)&Qs[row * AP + c4] = qv;
    }

    const int kiters = 2 * (qt + 1);

    // cp.async fill of one K/V stage (64 rows x 64 floats each)
    auto fill_stage = [&](int it) {
        const int s = it & 1;
        const int k0 = it * 64;
        const uint32_t kb = sb + (128 + 64 * s) * AP * 4;
        const uint32_t vb = sb + (256 + 64 * s) * AP * 4;
        #pragma unroll
        for (int i = 0; i < 4; i++) {
            int o = tid + 256 * i;
            int row = o >> 4, ch = o & 15;
            const size_t gro = (rowbase + k0 + row) * ND + coff + ch * 4;
            cpasync16(kb + row * (AP * 4) + ch * 16, Kg + gro);
            cpasync16(vb + row * (AP * 4) + ch * 16, V + gro);
        }
    };

    fill_stage(0); cp_commit();

    float m0v = -1e30f, m1v = -1e30f, l0 = 0.f, l1 = 0.f;
    float oacc[8][4];
    #pragma unroll
    for (int ni = 0; ni < 8; ni++)
        #pragma unroll
        for (int q = 0; q < 4; q++) oacc[ni][q] = 0.f;

    const int row0 = q0 + wm + r, row1 = row0 + 8;
    const int s0lane = 4 * r + (c >> 1);
    const bool sel = (c & 1);

    for (int it = 0; it < kiters; it++) {
        if (it + 1 < kiters) fill_stage(it + 1);
        cp_commit();
        asm volatile("cp.async.wait_group 1;" ::: "memory");
        __syncthreads();   // stage `it` resident CTA-wide

        const int s = it & 1;
        const int k0 = it * 64;
        const uint32_t* Ku = (const uint32_t*)(sm + (size_t)(128 + 64 * s) * AP);
        const uint32_t* Vu = (const uint32_t*)(sm + (size_t)(256 + 64 * s) * AP);
        const uint32_t* Qu = (const uint32_t*)Qs;

        // ---- S[16 x 64] = Qtile @ Ktile^T ----
        float sacc[8][4];
        #pragma unroll
        for (int ni = 0; ni < 8; ni++)
            #pragma unroll
            for (int q = 0; q < 4; q++) sacc[ni][q] = 0.f;

        #pragma unroll
        for (int kk = 0; kk < 8; kk++) {
            uint32_t a0 = Qu[(wm + r) * AP + kk * 8 + c];
            uint32_t a1 = Qu[(wm + r + 8) * AP + kk * 8 + c];
            uint32_t a2 = Qu[(wm + r) * AP + kk * 8 + c + 4];
            uint32_t a3 = Qu[(wm + r + 8) * AP + kk * 8 + c + 4];
            #pragma unroll
            for (int ni = 0; ni < 8; ni++) {
                uint32_t b0 = Ku[(ni * 8 + r) * AP + kk * 8 + c];
                uint32_t b1 = Ku[(ni * 8 + r) * AP + kk * 8 + c + 4];
                mma_tf32(sacc[ni], a0, a1, a2, a3, b0, b1);
            }
        }

        // ---- causal mask (only near diagonal) ----
        if (k0 + 63 > row0) {
            #pragma unroll
            for (int ni = 0; ni < 8; ni++) {
                const int col = k0 + ni * 8 + 2 * c;
                if (col > row0)     sacc[ni][0] = -1e30f;
                if (col + 1 > row0) sacc[ni][1] = -1e30f;
                if (col > row1)     sacc[ni][2] = -1e30f;
                if (col + 1 > row1) sacc[ni][3] = -1e30f;
            }
        }

        // ---- online softmax ----
        float rm0 = -1e30f, rm1 = -1e30f;
        #pragma unroll
        for (int ni = 0; ni < 8; ni++) {
            rm0 = fmaxf(rm0, fmaxf(sacc[ni][0], sacc[ni][1]));
            rm1 = fmaxf(rm1, fmaxf(sacc[ni][2], sacc[ni][3]));
        }
        rm0 = fmaxf(rm0, __shfl_xor_sync(0xffffffffu, rm0, 1));
        rm0 = fmaxf(rm0, __shfl_xor_sync(0xffffffffu, rm0, 2));
        rm1 = fmaxf(rm1, __shfl_xor_sync(0xffffffffu, rm1, 1));
        rm1 = fmaxf(rm1, __shfl_xor_sync(0xffffffffu, rm1, 2));

        const float mn0 = fmaxf(m0v, rm0), mn1 = fmaxf(m1v, rm1);
        const float corr0 = __expf(m0v - mn0), corr1 = __expf(m1v - mn1);
        float rs0 = 0.f, rs1 = 0.f;
        #pragma unroll
        for (int ni = 0; ni < 8; ni++) {
            float p0 = tf32r(__expf(sacc[ni][0] - mn0));
            float p1 = tf32r(__expf(sacc[ni][1] - mn0));
            float p2 = tf32r(__expf(sacc[ni][2] - mn1));
            float p3 = tf32r(__expf(sacc[ni][3] - mn1));
            sacc[ni][0] = p0; sacc[ni][1] = p1; sacc[ni][2] = p2; sacc[ni][3] = p3;
            rs0 += p0 + p1; rs1 += p2 + p3;
        }
        rs0 += __shfl_xor_sync(0xffffffffu, rs0, 1);
        rs0 += __shfl_xor_sync(0xffffffffu, rs0, 2);
        rs1 += __shfl_xor_sync(0xffffffffu, rs1, 1);
        rs1 += __shfl_xor_sync(0xffffffffu, rs1, 2);

        l0 = l0 * corr0 + rs0;  m0v = mn0;
        l1 = l1 * corr1 + rs1;  m1v = mn1;
        #pragma unroll
        for (int ni = 0; ni < 8; ni++) {
            oacc[ni][0] *= corr0; oacc[ni][1] *= corr0;
            oacc[ni][2] *= corr1; oacc[ni][3] *= corr1;
        }

        // ---- O[16 x 64] += P @ V ----
        // A-frag of O-mma built from S-frags via warp shuffles:
        //   a0 = P[row r][kk*8 + c]     <- lane 4r + (c>>1), value p[c&1]
        //   a2 = P[row r][kk*8 + c + 4] <- lane 4r + 2 + (c>>1)
        // B-frag reads natural-layout V by column (conflict-free).
        #pragma unroll
        for (int kk = 0; kk < 8; kk++) {
            float t0 = __shfl_sync(0xffffffffu, sacc[kk][0], s0lane);
            float t1 = __shfl_sync(0xffffffffu, sacc[kk][1], s0lane);
            float t2 = __shfl_sync(0xffffffffu, sacc[kk][2], s0lane);
            float t3 = __shfl_sync(0xffffffffu, sacc[kk][3], s0lane);
            float u0 = __shfl_sync(0xffffffffu, sacc[kk][0], s0lane + 2);
            float u1 = __shfl_sync(0xffffffffu, sacc[kk][1], s0lane + 2);
            float u2 = __shfl_sync(0xffffffffu, sacc[kk][2], s0lane + 2);
            float u3 = __shfl_sync(0xffffffffu, sacc[kk][3], s0lane + 2);
            uint32_t a0 = __float_as_uint(sel ? t1 : t0);
            uint32_t a1 = __float_as_uint(sel ? t3 : t2);
            uint32_t a2 = __float_as_uint(sel ? u1 : u0);
            uint32_t a3 = __float_as_uint(sel ? u3 : u2);
            #pragma unroll
            for (int ni = 0; ni < 8; ni++) {
                uint32_t b0 = Vu[(kk * 8 + c) * AP + ni * 8 + r];
                uint32_t b1 = Vu[(kk * 8 + c + 4) * AP + ni * 8 + r];
                mma_tf32(oacc[ni], a0, a1, a2, a3, b0, b1);
            }
        }
        __syncthreads();   // done reading stage `it`; next iter may overwrite it
    }

    // ---- epilogue: normalize, tf32-round (final GEMM input), store ----
    const float inv0 = 1.f / l0, inv1 = 1.f / l1;
    #pragma unroll
    for (int ni = 0; ni < 8; ni++) {
        const int col = coff + ni * 8 + 2 * c;
        *(float2*)&O[(rowbase + row0) * ND + col] =
            make_float2(tf32r(oacc[ni][0] * inv0), tf32r(oacc[ni][1] * inv0));
        *(float2*)&O[(rowbase + row1) * ND + col] =
            make_float2(tf32r(oacc[ni][2] * inv1), tf32r(oacc[ni][3] * inv1));
    }
}

// ---------------------------------------------------------------------------
extern "C" void kernel_launch(void* const* d_in, const int* in_sizes, int n_in,
                              void* d_out, int out_size)
{
    const float* x  = (const float*)d_in[0];
    const float* Wq = (const float*)d_in[1];
    const float* bq = (const float*)d_in[2];
    const float* Wk = (const float*)d_in[3];
    const float* bk = (const float*)d_in[4];
    const float* Wv = (const float*)d_in[5];
    const float* bv = (const float*)d_in[6];
    const float* Wf = (const float*)d_in[7];
    const float* bf = (const float*)d_in[8];
    float* out = (float*)d_out;

    void *pq, *pk, *pv, *patt, *pxr, *pwr;
    cudaGetSymbolAddress(&pq,   g_q);
    cudaGetSymbolAddress(&pk,   g_k);
    cudaGetSymbolAddress(&pv,   g_v);
    cudaGetSymbolAddress(&patt, g_att);
    cudaGetSymbolAddress(&pxr,  g_xr);
    cudaGetSymbolAddress(&pwr,  g_wr);
    float* xr = (float*)pxr;
    float* wr = (float*)pwr;   // [4][ND*ND]

    cudaFuncSetAttribute(gemm_qkv,
                         cudaFuncAttributeMaxDynamicSharedMemorySize, GEMM_SMEM);
    cudaFuncSetAttribute(gemm_out,
                         cudaFuncAttributeMaxDynamicSharedMemorySize, GEMM_SMEM);
    cudaFuncSetAttribute(attn_tc,
                         cudaFuncAttributeMaxDynamicSharedMemorySize, ATTN_SMEM);

    // tf32-round GEMM inputs
    const int n4x = NM * ND / 4;
    const int n4w = ND * ND / 4;
    round_kernel<<<n4x / 256, 256>>>((const float4*)x,  (float4*)xr, n4x);
    round_kernel<<<n4w / 256, 256>>>((const float4*)Wq, (float4*)(wr + 0 * ND * ND), n4w);
    round_kernel<<<n4w / 256, 256>>>((const float4*)Wk, (float4*)(wr + 1 * ND * ND), n4w);
    round_kernel<<<n4w / 256, 256>>>((const float4*)Wv, (float4*)(wr + 2 * ND * ND), n4w);
    round_kernel<<<n4w / 256, 256>>>((const float4*)Wf, (float4*)(wr + 3 * ND * ND), n4w);

    dim3 qkvgrid(ND / BN, NM / BM, 3);   // (8, 32, 3)
    gemm_qkv<<<qkvgrid, 256, GEMM_SMEM>>>(
        xr, wr + 0 * ND * ND, wr + 1 * ND * ND, wr + 2 * ND * ND,
        bq, bk, bv, (float*)pq, (float*)pk, (float*)pv);

    dim3 agrid(NS / 128, NB * NH);       // (16, 32)
    attn_tc<<<agrid, 256, ATTN_SMEM>>>((const float*)pq, (const float*)pk,
                                       (const float*)pv, (float*)patt);

    dim3 ggrid(ND / BN, NM / BM);        // (8, 32)
    gemm_out<<<ggrid, 256, GEMM_SMEM>>>((const float*)patt, wr + 3 * ND * ND, bf, out);
}